// round 11
// baseline (speedup 1.0000x reference)
#include <cuda_runtime.h>
#include <cuda_bf16.h>
#include <math.h>

// FusedCirculantBlock: SignFlip -> per-block rFFT(512) -> 8x8 spectral mix -> irFFT -> bias -> erf-GELU
// B=2, S=4096, F_IN=F_OUT=4096, P=512, Q_IN=Q_OUT=8.
//
// R3: smem-traffic-minimized version. 256 threads/CTA, one token PAIR per CTA,
// 3 CTAs/SM. Forward stage-0 fused with global load+signflip (registers),
// inverse stage-2 fused with bias+GELU epilogue (registers->global).
// Twiddles built by register recurrence from one LDS base value.
// FFT groups (64 threads) sync via their own named barrier; only 2 CTA-wide
// syncs per pair (around the all-to-all spectral mix). Wf/bias stay in L2.

#define QB 8            // blocks per side
#define NF 257          // rfft bins
#define FFTPAD 576      // 512 + 512/8 padding slots
#define TPB 256

__device__ float2   g_tw[512];          // exp(-2*pi*i*k/512)
__device__ unsigned g_sfbits[128];      // sign bits packed
__device__ float4   g_Wfp[64 * NF];     // [opair][i][f] -> (reE,imE,reO,imO), scaled 1/1024

static __device__ __forceinline__ int PAD(int i) { return i + (i >> 3); }

static __device__ __forceinline__ void bar64(int id) {
    asm volatile("bar.sync %0, %1;" :: "r"(id), "r"(64) : "memory");
}

static __device__ __forceinline__ float2 cadd(float2 a, float2 b) { return make_float2(a.x + b.x, a.y + b.y); }
static __device__ __forceinline__ float2 csub(float2 a, float2 b) { return make_float2(a.x - b.x, a.y - b.y); }
static __device__ __forceinline__ float2 cmul(float2 a, float2 w) {
    return make_float2(a.x * w.x - a.y * w.y, a.x * w.y + a.y * w.x);
}
static __device__ __forceinline__ float2 cfma(float2 x, float2 w, float2 acc) {
    acc.x = fmaf(x.x, w.x, fmaf(-x.y, w.y, acc.x));
    acc.y = fmaf(x.x, w.y, fmaf(x.y, w.x, acc.y));
    return acc;
}

static __device__ __forceinline__ float gelu_erf(float v) {
    return 0.5f * v * (1.0f + erff(v * 0.70710678118654752f));
}

// 8-point DFT: b_u = sum_r a_r * w8^{u*r}; w8 = exp(-2*pi*i/8) fwd (INV=0), conj for INV=1
template <int INV>
static __device__ __forceinline__ void dft8(float2 a[8]) {
    const float C = 0.70710678118654752f;
    float2 s0 = cadd(a[0], a[4]), s1 = csub(a[0], a[4]);
    float2 s2 = cadd(a[2], a[6]), s3 = csub(a[2], a[6]);
    float2 u0 = cadd(a[1], a[5]), u1 = csub(a[1], a[5]);
    float2 u2 = cadd(a[3], a[7]), u3 = csub(a[3], a[7]);
    float2 E0 = cadd(s0, s2), E2 = csub(s0, s2);
    float2 O0 = cadd(u0, u2), O2 = csub(u0, u2);
    float2 E1, E3, O1, O3, t1, t2, t3;
    if (!INV) {
        E1 = make_float2(s1.x + s3.y, s1.y - s3.x);   // s1 - i*s3
        E3 = make_float2(s1.x - s3.y, s1.y + s3.x);   // s1 + i*s3
        O1 = make_float2(u1.x + u3.y, u1.y - u3.x);
        O3 = make_float2(u1.x - u3.y, u1.y + u3.x);
        t1 = make_float2(C * (O1.x + O1.y), C * (O1.y - O1.x));   // c(1-i)*O1
        t2 = make_float2(O2.y, -O2.x);                            // -i*O2
        t3 = make_float2(C * (O3.y - O3.x), -C * (O3.x + O3.y));  // -c(1+i)*O3
    } else {
        E1 = make_float2(s1.x - s3.y, s1.y + s3.x);   // s1 + i*s3
        E3 = make_float2(s1.x + s3.y, s1.y - s3.x);
        O1 = make_float2(u1.x - u3.y, u1.y + u3.x);
        O3 = make_float2(u1.x + u3.y, u1.y - u3.x);
        t1 = make_float2(C * (O1.x - O1.y), C * (O1.x + O1.y));   // c(1+i)*O1
        t2 = make_float2(-O2.y, O2.x);                            // +i*O2
        t3 = make_float2(-C * (O3.x + O3.y), C * (O3.x - O3.y));  // c(-1+i)*O3
    }
    a[0] = cadd(E0, O0); a[4] = csub(E0, O0);
    a[1] = cadd(E1, t1); a[5] = csub(E1, t1);
    a[2] = cadd(E2, t2); a[6] = csub(E2, t2);
    a[3] = cadd(E3, t3); a[7] = csub(E3, t3);
}

// Build w^2..w^7 from w with short chains (max depth 3 cmuls).
static __device__ __forceinline__ void wpow7(const float2 w1, float2 w[8]) {
    w[1] = w1;
    w[2] = cmul(w1, w1);
    w[3] = cmul(w[2], w1);
    w[4] = cmul(w[2], w[2]);
    w[5] = cmul(w[3], w[2]);
    w[6] = cmul(w[3], w[3]);
    w[7] = cmul(w[4], w[3]);
}

// ---------------- precompute kernels (run inside the graph, cheap) ----------

__global__ void precompute_tw_sf(const int* __restrict__ sign_bits) {
    int k = threadIdx.x;  // 512 threads
    float s, c;
    sincospif((float)k / 256.0f, &s, &c);   // angle = 2*pi*k/512
    g_tw[k] = make_float2(c, -s);
    if (k < 128) {
        unsigned m = 0;
        #pragma unroll 4
        for (int b = 0; b < 32; b++)
            m |= ((unsigned)sign_bits[k * 32 + b] & 1u) << b;
        g_sfbits[k] = m;
    }
}

__global__ void precompute_wf(const float* __restrict__ w) {
    __shared__ float2 stw[512];
    __shared__ float  sw[512];
    int blk = blockIdx.x;           // o*8+i
    int o = blk >> 3, i = blk & 7;
    int opair = o >> 1, slot = o & 1;
    for (int k = threadIdx.x; k < 512; k += blockDim.x) {
        stw[k] = g_tw[k];
        sw[k] = w[blk * 512 + k];
    }
    __syncthreads();
    for (int f = threadIdx.x; f <= 256; f += blockDim.x) {
        float re = 0.0f, im = 0.0f;
        for (int n = 0; n < 512; n++) {
            float2 t = stw[(f * n) & 511];
            float wv = sw[n];
            re = fmaf(wv, t.x, re);
            im = fmaf(wv, t.y, im);
        }
        // fold 1/2 (rfft pack skips /2 -> X stored as 2X) and 1/512 (inverse scale)
        float2* dst = ((float2*)g_Wfp) + ((size_t)((opair * QB + i) * NF + f) * 2 + slot);
        *dst = make_float2(re * (1.0f / 1024.0f), im * (1.0f / 1024.0f));
    }
}

// ---------------- main fused kernel ----------------------------------------
// grid = BS/2 blocks, 256 threads, 3 CTAs/SM.
// SMEM (float2): tw[512] | ping[4*576] | pong[4*576] | Xf[2*8*257] (reused as
// inverse scratch S) | bits[128 u32]

__global__ void __launch_bounds__(TPB, 3)
fused_main(const float* __restrict__ x, const float* __restrict__ bias,
           float* __restrict__ out) {
    extern __shared__ float2 sm[];
    float2*   s_tw  = sm;                     // 512
    float2*   ping  = sm + 512;               // 2304
    float2*   pong  = ping + 4 * FFTPAD;      // 2304
    float2*   s_Xf  = pong + 4 * FFTPAD;      // 4112
    unsigned* s_bits = (unsigned*)(s_Xf + 2 * QB * NF);  // 128 u32

    const int tid = threadIdx.x;
    const int j   = tid >> 6;       // fft group / output-pair id 0..3
    const int t6  = tid & 63;
    const int bid = j + 1;          // named barrier for this group

    for (int k = tid; k < 512; k += TPB) s_tw[k] = g_tw[k];
    if (tid < 128) s_bits[tid] = g_sfbits[tid];
    __syncthreads();

    const long long tok0 = (long long)blockIdx.x * 2;
    float2* Pg = ping + j * FFTPAD;
    float2* Qg = pong + j * FFTPAD;
    const int q = t6 & 7, p3 = t6 >> 3;

    // ---------------- forward FFTs (both tokens) ----------------
    #pragma unroll 1
    for (int tk = 0; tk < 2; tk++) {
        const float* xr = x + (tok0 + tk) * 4096 + j * 1024;
        float2 a[8];
        // stage 0 fused with global load + sign flip (p = t6)
        #pragma unroll
        for (int r = 0; r < 8; r++) {
            int n = t6 + 64 * r;
            int e0 = j * 1024 + n, e1 = e0 + 512;
            unsigned b0 = (s_bits[e0 >> 5] >> (e0 & 31)) & 1u;
            unsigned b1 = (s_bits[e1 >> 5] >> (e1 & 31)) & 1u;
            a[r].x = __int_as_float(__float_as_int(xr[n])       ^ (b0 << 31));
            a[r].y = __int_as_float(__float_as_int(xr[n + 512]) ^ (b1 << 31));
        }
        dft8<0>(a);
        {
            float2 w[8]; wpow7(s_tw[t6], w);
            Qg[PAD(8 * t6)] = a[0];
            #pragma unroll
            for (int u = 1; u < 8; u++) Qg[PAD(8 * t6 + u)] = cmul(a[u], w[u]);
        }
        bar64(bid);
        // stage 1 (q = t6&7, p = t6>>3)
        #pragma unroll
        for (int r = 0; r < 8; r++) a[r] = Qg[PAD(q + 8 * p3 + 64 * r)];
        dft8<0>(a);
        {
            float2 w[8]; wpow7(s_tw[8 * p3], w);
            Pg[PAD(q + 64 * p3)] = a[0];
            #pragma unroll
            for (int u = 1; u < 8; u++) Pg[PAD(q + 64 * p3 + 8 * u)] = cmul(a[u], w[u]);
        }
        bar64(bid);
        // stage 2 (no twiddles)
        #pragma unroll
        for (int r = 0; r < 8; r++) a[r] = Pg[PAD(t6 + 64 * r)];
        dft8<0>(a);
        #pragma unroll
        for (int u = 0; u < 8; u++) Qg[PAD(t6 + 64 * u)] = a[u];
        bar64(bid);
        // unpack Z -> X_{2j}, X_{2j+1} (2*X; the 1/2 is folded into Wf)
        float2* X0 = s_Xf + tk * (QB * NF) + (2 * j) * NF;
        float2* X1 = X0 + NF;
        for (int f = t6; f <= 256; f += 64) {
            float2 zf = Qg[PAD(f)];
            float2 zm = Qg[PAD((512 - f) & 511)];
            X0[f] = make_float2(zf.x + zm.x, zf.y - zm.y);   //   Z + conj(Zm)
            X1[f] = make_float2(zf.y + zm.y, zm.x - zf.x);   // -i(Z - conj(Zm))
        }
        bar64(bid);   // Qg free for next token's stage-0 writes
    }
    __syncthreads();   // all groups' Xf ready (all-to-all read next)

    // ---------------- 8x8 spectral mix + Hermitian pack ---------------------
    // group j computes output blocks (2j, 2j+1); Zb(tk=0)->ping, (tk=1)->pong
    for (int f = t6; f <= 256; f += 64) {
        const float4* Wp = g_Wfp + (size_t)(j * QB) * NF + f;
        float4 wv[8];
        #pragma unroll
        for (int i = 0; i < 8; i++) wv[i] = Wp[i * NF];
        #pragma unroll
        for (int tk = 0; tk < 2; tk++) {
            const float2* Xp = s_Xf + tk * (QB * NF) + f;
            float2 y0 = make_float2(0.f, 0.f), y1 = make_float2(0.f, 0.f);
            #pragma unroll
            for (int i = 0; i < 8; i++) {
                float2 xv = Xp[i * NF];
                y0 = cfma(xv, make_float2(wv[i].x, wv[i].y), y0);
                y1 = cfma(xv, make_float2(wv[i].z, wv[i].w), y1);
            }
            float2* Zb = (tk ? Qg : Pg);
            if (f == 0 || f == 256) {
                Zb[PAD(f)] = make_float2(y0.x, y1.x);  // DC/Nyquist: real parts
            } else {
                Zb[PAD(f)]       = make_float2(y0.x - y1.y, y0.y + y1.x); // Y0 + i*Y1
                Zb[PAD(512 - f)] = make_float2(y0.x + y1.y, y1.x - y0.y); // conj ext.
            }
        }
    }
    __syncthreads();   // all mixes done; Xf region now reusable as scratch S

    // ---------------- inverse FFTs + fused epilogue --------------------------
    float2* Sg = s_Xf + j * FFTPAD;   // 4*576 = 2304 <= 4112
    #pragma unroll 1
    for (int tk = 0; tk < 2; tk++) {
        float2* Zg = (tk ? Qg : Pg);
        float2 a[8];
        // inv stage 0 (p = t6): Zg -> Sg
        #pragma unroll
        for (int r = 0; r < 8; r++) a[r] = Zg[PAD(t6 + 64 * r)];
        dft8<1>(a);
        {
            float2 b = s_tw[t6]; b.y = -b.y;       // conj
            float2 w[8]; wpow7(b, w);
            Sg[PAD(8 * t6)] = a[0];
            #pragma unroll
            for (int u = 1; u < 8; u++) Sg[PAD(8 * t6 + u)] = cmul(a[u], w[u]);
        }
        bar64(bid);
        // inv stage 1: Sg -> Zg
        #pragma unroll
        for (int r = 0; r < 8; r++) a[r] = Sg[PAD(q + 8 * p3 + 64 * r)];
        dft8<1>(a);
        {
            float2 b = s_tw[8 * p3]; b.y = -b.y;
            float2 w[8]; wpow7(b, w);
            Zg[PAD(q + 64 * p3)] = a[0];
            #pragma unroll
            for (int u = 1; u < 8; u++) Zg[PAD(q + 64 * p3 + 8 * u)] = cmul(a[u], w[u]);
        }
        bar64(bid);
        // inv stage 2 fused with bias + erf-GELU epilogue (registers -> global)
        #pragma unroll
        for (int r = 0; r < 8; r++) a[r] = Zg[PAD(t6 + 64 * r)];
        dft8<1>(a);
        {
            const float* br   = bias + j * 1024;
            float*       orow = out + (tok0 + tk) * 4096 + j * 1024;
            #pragma unroll
            for (int u = 0; u < 8; u++) {
                int n = t6 + 64 * u;
                orow[n]       = gelu_erf(a[u].x + br[n]);
                orow[n + 512] = gelu_erf(a[u].y + br[n + 512]);
            }
        }
        // no barrier needed: tk=1 touches Sg only after its own group's
        // stage-1 barrier ordered all Sg reads of tk=0.
    }
}

// ---------------- launch ----------------------------------------------------

extern "C" void kernel_launch(void* const* d_in, const int* in_sizes, int n_in,
                              void* d_out, int out_size) {
    const float* x         = (const float*)d_in[0];
    const float* w         = (const float*)d_in[1];
    const float* bias      = (const float*)d_in[2];
    const int*   sign_bits = (const int*)d_in[3];
    float* out = (float*)d_out;

    const int BS = in_sizes[0] / 4096;   // 8192 tokens

    // SMEM: (512 + 2*4*576 + 2*8*257) float2 + 128 u32 = 74368 B -> 3 CTAs/SM
    const size_t smem = (size_t)(512 + 2 * 4 * FFTPAD + 2 * QB * NF) * sizeof(float2)
                      + 128 * sizeof(unsigned);

    cudaFuncSetAttribute(fused_main, cudaFuncAttributeMaxDynamicSharedMemorySize, (int)smem);

    precompute_tw_sf<<<1, 512>>>(sign_bits);
    precompute_wf<<<64, 256>>>(w);
    fused_main<<<BS / 2, TPB, smem>>>(x, bias, out);
}

// round 14
// speedup vs baseline: 1.0245x; 1.0245x over previous
#include <cuda_runtime.h>
#include <cuda_bf16.h>
#include <math.h>

// FusedCirculantBlock R4b: token-paired f32x2 FFT path.
// Both tokens of a pair ride the two lanes of packed f32x2 ops (same twiddles),
// halving FFT instruction count. Smem slots are 16B (re0,re1,im0,im1) with XOR
// swizzle. The rfft unpack is folded into the spectral mix via precombined
// weights Wa = W0 - i*W1, Wb = W0 + i*W1 (mix reads raw FFT output Z).
// vs R4: sub2 implemented as fma.rn.f32x2 with -1 (sub.rn.f32x2 may not be
// valid PTX; only add/mul/fma f32x2 forms are documented).

typedef unsigned long long ull;

#define QB 8
#define NF 257
#define TPB 256
#define SGN2 0x8000000080000000ULL
#define NEG1_2 0xBF800000BF800000ULL   // (-1.0f, -1.0f)

__device__ float2   g_tw[512];        // (c, -s) scalar (precompute use)
__device__ float4   g_tw4[512];       // (c, c, -s, -s) packed
__device__ unsigned g_sfbits[128];
__device__ float2   g_Wf[64 * NF];    // scalar spectra [o*8+i][f], scaled 1/1024
__device__ float4   g_WA[16 * NF];    // (waE.re, waE.im, waO.re, waO.im) per (j*4+i, f)
__device__ float4   g_WB[16 * NF];

struct __align__(16) cpx { ull re, im; };

static __device__ __forceinline__ int SWZ(int i) { return i ^ ((i >> 3) & 7); }

static __device__ __forceinline__ void bar64(int id) {
    asm volatile("bar.sync %0, %1;" :: "r"(id), "r"(64) : "memory");
}

static __device__ __forceinline__ ull add2(ull a, ull b){ ull d; asm("add.rn.f32x2 %0,%1,%2;":"=l"(d):"l"(a),"l"(b)); return d; }
static __device__ __forceinline__ ull mul2(ull a, ull b){ ull d; asm("mul.rn.f32x2 %0,%1,%2;":"=l"(d):"l"(a),"l"(b)); return d; }
static __device__ __forceinline__ ull fma2(ull a, ull b, ull c){ ull d; asm("fma.rn.f32x2 %0,%1,%2,%3;":"=l"(d):"l"(a),"l"(b),"l"(c)); return d; }
// a - b == fma(b, -1, a): exact (mul by -1 exact, single rounding on the add)
static __device__ __forceinline__ ull sub2(ull a, ull b){ return fma2(b, NEG1_2, a); }
static __device__ __forceinline__ ull pk2(float x, float y){ ull d; asm("mov.b64 %0,{%1,%2};":"=l"(d):"f"(x),"f"(y)); return d; }
static __device__ __forceinline__ ull bc2(float x){ ull d; asm("mov.b64 %0,{%1,%1};":"=l"(d):"f"(x)); return d; }
static __device__ __forceinline__ void up2(ull a, float& x, float& y){ asm("mov.b64 {%0,%1},%2;":"=f"(x),"=f"(y):"l"(a)); }

static __device__ __forceinline__ float gelu_erf(float v) {
    return 0.5f * v * (1.0f + erff(v * 0.70710678118654752f));
}

// packed complex mul (general)
static __device__ __forceinline__ cpx cmulp(cpx a, cpx b) {
    cpx r;
    r.re = fma2(a.im ^ SGN2, b.im, mul2(a.re, b.re));
    r.im = fma2(a.im, b.re, mul2(a.re, b.im));
    return r;
}

// a * w, w = (wx + i*wy) packed per-component
static __device__ __forceinline__ cpx cmultw(cpx a, cpx w) {
    cpx r;
    r.re = fma2(a.im, w.im ^ SGN2, mul2(a.re, w.re));
    r.im = fma2(a.im, w.re, mul2(a.re, w.im));
    return r;
}

static __device__ __forceinline__ void wpow7p(cpx w1, cpx w[8]) {
    w[1] = w1;
    w[2] = cmulp(w1, w1);
    w[3] = cmulp(w[2], w1);
    w[4] = cmulp(w[2], w[2]);
    w[5] = cmulp(w[3], w[2]);
    w[6] = cmulp(w[3], w[3]);
    w[7] = cmulp(w[4], w[3]);
}

// 8-point DFT on token-packed data. INV=0 fwd (w8=e^{-2pi i/8}), INV=1 conj.
template <int INV>
static __device__ __forceinline__ void dft8p(cpx a[8]) {
    const ull C2  = 0x3F3504F33F3504F3ULL;   // ( c,  c), c = 1/sqrt(2)
    const ull C2N = 0xBF3504F3BF3504F3ULL;   // (-c, -c)
    cpx s0 = { add2(a[0].re, a[4].re), add2(a[0].im, a[4].im) };
    cpx s1 = { sub2(a[0].re, a[4].re), sub2(a[0].im, a[4].im) };
    cpx s2 = { add2(a[2].re, a[6].re), add2(a[2].im, a[6].im) };
    cpx s3 = { sub2(a[2].re, a[6].re), sub2(a[2].im, a[6].im) };
    cpx u0 = { add2(a[1].re, a[5].re), add2(a[1].im, a[5].im) };
    cpx u1 = { sub2(a[1].re, a[5].re), sub2(a[1].im, a[5].im) };
    cpx u2 = { add2(a[3].re, a[7].re), add2(a[3].im, a[7].im) };
    cpx u3 = { sub2(a[3].re, a[7].re), sub2(a[3].im, a[7].im) };
    cpx E0 = { add2(s0.re, s2.re), add2(s0.im, s2.im) };
    cpx E2 = { sub2(s0.re, s2.re), sub2(s0.im, s2.im) };
    cpx O0 = { add2(u0.re, u2.re), add2(u0.im, u2.im) };
    cpx O2 = { sub2(u0.re, u2.re), sub2(u0.im, u2.im) };
    cpx E1, E3, O1, O3, t1, t2, t3;
    if (!INV) {
        E1.re = add2(s1.re, s3.im); E1.im = sub2(s1.im, s3.re);   // s1 - i*s3
        E3.re = sub2(s1.re, s3.im); E3.im = add2(s1.im, s3.re);   // s1 + i*s3
        O1.re = add2(u1.re, u3.im); O1.im = sub2(u1.im, u3.re);
        O3.re = sub2(u1.re, u3.im); O3.im = add2(u1.im, u3.re);
        t1.re = mul2(add2(O1.re, O1.im), C2);  t1.im = mul2(sub2(O1.im, O1.re), C2);
        t2.re = O2.im;                         t2.im = O2.re ^ SGN2;
        t3.re = mul2(sub2(O3.im, O3.re), C2);  t3.im = mul2(add2(O3.re, O3.im), C2N);
    } else {
        E1.re = sub2(s1.re, s3.im); E1.im = add2(s1.im, s3.re);   // s1 + i*s3
        E3.re = add2(s1.re, s3.im); E3.im = sub2(s1.im, s3.re);
        O1.re = sub2(u1.re, u3.im); O1.im = add2(u1.im, u3.re);
        O3.re = add2(u1.re, u3.im); O3.im = sub2(u1.im, u3.re);
        t1.re = mul2(sub2(O1.re, O1.im), C2);  t1.im = mul2(add2(O1.re, O1.im), C2);
        t2.re = O2.im ^ SGN2;                  t2.im = O2.re;
        t3.re = mul2(add2(O3.re, O3.im), C2N); t3.im = mul2(sub2(O3.re, O3.im), C2);
    }
    a[0].re = add2(E0.re, O0.re); a[0].im = add2(E0.im, O0.im);
    a[4].re = sub2(E0.re, O0.re); a[4].im = sub2(E0.im, O0.im);
    a[1].re = add2(E1.re, t1.re); a[1].im = add2(E1.im, t1.im);
    a[5].re = sub2(E1.re, t1.re); a[5].im = sub2(E1.im, t1.im);
    a[2].re = add2(E2.re, t2.re); a[2].im = add2(E2.im, t2.im);
    a[6].re = sub2(E2.re, t2.re); a[6].im = sub2(E2.im, t2.im);
    a[3].re = add2(E3.re, t3.re); a[3].im = add2(E3.im, t3.im);
    a[7].re = sub2(E3.re, t3.re); a[7].im = sub2(E3.im, t3.im);
}

// ---------------- precompute (in-graph, cheap) ------------------------------

__global__ void precompute_tw_sf(const int* __restrict__ sign_bits) {
    int k = threadIdx.x;  // 512
    float s, c;
    sincospif((float)k / 256.0f, &s, &c);
    g_tw[k]  = make_float2(c, -s);
    g_tw4[k] = make_float4(c, c, -s, -s);
    if (k < 128) {
        unsigned m = 0;
        #pragma unroll 4
        for (int b = 0; b < 32; b++)
            m |= ((unsigned)sign_bits[k * 32 + b] & 1u) << b;
        g_sfbits[k] = m;
    }
}

__global__ void precompute_wf(const float* __restrict__ w) {
    __shared__ float2 stw[512];
    __shared__ float  sw[512];
    int blk = blockIdx.x;  // o*8+i
    for (int k = threadIdx.x; k < 512; k += blockDim.x) {
        stw[k] = g_tw[k];
        sw[k] = w[blk * 512 + k];
    }
    __syncthreads();
    for (int f = threadIdx.x; f <= 256; f += blockDim.x) {
        float re = 0.0f, im = 0.0f;
        for (int n = 0; n < 512; n++) {
            float2 t = stw[(f * n) & 511];
            float wv = sw[n];
            re = fmaf(wv, t.x, re);
            im = fmaf(wv, t.y, im);
        }
        g_Wf[blk * NF + f] = make_float2(re * (1.0f / 1024.0f), im * (1.0f / 1024.0f));
    }
}

// Wa = W_{o,2i} - i*W_{o,2i+1},  Wb = W_{o,2i} + i*W_{o,2i+1};
// packed per (j,i,f) for outputs o = 2j (x,y) and o = 2j+1 (z,w).
__global__ void precompute_combine() {
    int idx = blockIdx.x * blockDim.x + threadIdx.x;
    if (idx >= 16 * NF) return;
    int f = idx % NF, r = idx / NF;
    int j = r >> 2, i = r & 3;
    float2 WE0 = g_Wf[((2 * j)     * QB + 2 * i)     * NF + f];
    float2 WO0 = g_Wf[((2 * j)     * QB + 2 * i + 1) * NF + f];
    float2 WE1 = g_Wf[((2 * j + 1) * QB + 2 * i)     * NF + f];
    float2 WO1 = g_Wf[((2 * j + 1) * QB + 2 * i + 1) * NF + f];
    g_WA[idx] = make_float4(WE0.x + WO0.y, WE0.y - WO0.x, WE1.x + WO1.y, WE1.y - WO1.x);
    g_WB[idx] = make_float4(WE0.x - WO0.y, WE0.y + WO0.x, WE1.x - WO1.y, WE1.y + WO1.x);
}

// ---------------- main fused kernel -----------------------------------------
// grid = BS/2, 256 thr, 2 CTAs/SM. Smem cpx slots (16B):
//   tw[512] | A[4*512] | B[4*512] | C[4*512] | bits[128 u32]  = 107008 B

__global__ void __launch_bounds__(TPB, 2)
fused_main(const float* __restrict__ x, const float* __restrict__ bias,
           float* __restrict__ out) {
    extern __shared__ cpx sm[];
    cpx* s_tw = sm;                 // 512
    cpx* s_A  = sm + 512;           // 2048
    cpx* s_B  = sm + 512 + 2048;    // 2048
    cpx* s_C  = sm + 512 + 4096;    // 2048
    unsigned* s_bits = (unsigned*)(sm + 512 + 6144);

    const int tid = threadIdx.x;
    const int j   = tid >> 6;        // group / output-pair id
    const int t6  = tid & 63;
    const int q   = t6 & 7, p3 = t6 >> 3;
    const int bid = j + 1;

    {
        float4* twd = (float4*)s_tw;
        for (int k = tid; k < 512; k += TPB) twd[k] = g_tw4[k];
        if (tid < 128) s_bits[tid] = g_sfbits[tid];
    }
    __syncthreads();

    const long long tok0 = (long long)blockIdx.x * 2;
    cpx* Ag = s_A + j * 512;
    cpx* Bg = s_B + j * 512;
    cpx* Cg = s_C + j * 512;

    // ---------------- forward FFT (both tokens packed) ----------------
    cpx a[8];
    {   // stage 0: global load + sign flip + dft -> B
        const float* x0 = x + tok0 * 4096 + j * 1024;
        const float* x1 = x0 + 4096;
        #pragma unroll
        for (int r = 0; r < 8; r++) {
            int n = t6 + 64 * r;
            int e0 = j * 1024 + n, e1 = e0 + 512;
            ull m0 = (0ULL - (ull)((s_bits[e0 >> 5] >> (e0 & 31)) & 1u)) & SGN2;
            ull m1 = (0ULL - (ull)((s_bits[e1 >> 5] >> (e1 & 31)) & 1u)) & SGN2;
            a[r].re = pk2(x0[n],       x1[n])       ^ m0;
            a[r].im = pk2(x0[n + 512], x1[n + 512]) ^ m1;
        }
        dft8p<0>(a);
        cpx w[8]; wpow7p(s_tw[t6], w);
        Bg[SWZ(8 * t6)] = a[0];
        #pragma unroll
        for (int u = 1; u < 8; u++) Bg[SWZ(8 * t6 + u)] = cmultw(a[u], w[u]);
    }
    bar64(bid);
    {   // stage 1: B -> A
        #pragma unroll
        for (int r = 0; r < 8; r++) a[r] = Bg[SWZ(q + 8 * p3 + 64 * r)];
        dft8p<0>(a);
        cpx w[8]; wpow7p(s_tw[8 * p3], w);
        Ag[SWZ(q + 64 * p3)] = a[0];
        #pragma unroll
        for (int u = 1; u < 8; u++) Ag[SWZ(q + 64 * p3 + 8 * u)] = cmultw(a[u], w[u]);
    }
    bar64(bid);
    {   // stage 2: A -> B (no twiddles)
        #pragma unroll
        for (int r = 0; r < 8; r++) a[r] = Ag[SWZ(t6 + 64 * r)];
        dft8p<0>(a);
        #pragma unroll
        for (int u = 0; u < 8; u++) Bg[SWZ(t6 + 64 * u)] = a[u];
    }
    __syncthreads();   // all groups' Z in B; A dead

    // ---------------- mix (unpack folded in) + Hermitian pack -> A ----------
    for (int f = t6; f <= 256; f += 64) {
        ull ReP0 = 0, ReM0 = 0, ImP0 = 0, ImM0 = 0;
        ull ReP1 = 0, ReM1 = 0, ImP1 = 0, ImM1 = 0;
        int fm = (512 - f) & 511;
        #pragma unroll
        for (int i = 0; i < 4; i++) {
            cpx zf = s_B[i * 512 + SWZ(f)];
            cpx zm = s_B[i * 512 + SWZ(fm)];
            float4 wa = __ldg(&g_WA[(j * 4 + i) * NF + f]);
            float4 wb = __ldg(&g_WB[(j * 4 + i) * NF + f]);
            ull ar0 = bc2(wa.x), ai0 = bc2(wa.y), br0 = bc2(wb.x), bi0 = bc2(wb.y);
            ull ar1 = bc2(wa.z), ai1 = bc2(wa.w), br1 = bc2(wb.z), bi1 = bc2(wb.w);
            // y += zf*wa  (re: +zr*ar -zi*ai ; im: +zr*ai +zi*ar)
            ReP0 = fma2(zf.re, ar0, ReP0); ReM0 = fma2(zf.im, ai0, ReM0);
            ImP0 = fma2(zf.re, ai0, ImP0); ImP0 = fma2(zf.im, ar0, ImP0);
            ReP1 = fma2(zf.re, ar1, ReP1); ReM1 = fma2(zf.im, ai1, ReM1);
            ImP1 = fma2(zf.re, ai1, ImP1); ImP1 = fma2(zf.im, ar1, ImP1);
            // y += conj(zm)*wb (re: +zr*br +zi*bi ; im: +zr*bi -zi*br)
            ReP0 = fma2(zm.re, br0, ReP0); ReP0 = fma2(zm.im, bi0, ReP0);
            ImP0 = fma2(zm.re, bi0, ImP0); ImM0 = fma2(zm.im, br0, ImM0);
            ReP1 = fma2(zm.re, br1, ReP1); ReP1 = fma2(zm.im, bi1, ReP1);
            ImP1 = fma2(zm.re, bi1, ImP1); ImM1 = fma2(zm.im, br1, ImM1);
        }
        ull y0re = sub2(ReP0, ReM0), y0im = sub2(ImP0, ImM0);
        ull y1re = sub2(ReP1, ReM1), y1im = sub2(ImP1, ImM1);
        if (f == 0 || f == 256) {
            cpx v; v.re = y0re; v.im = y1re;   // DC/Nyquist: imag analytically 0
            Ag[SWZ(f)] = v;
        } else {
            cpx v1; v1.re = sub2(y0re, y1im); v1.im = add2(y0im, y1re);  // Y0 + i*Y1
            cpx v2; v2.re = add2(y0re, y1im); v2.im = sub2(y1re, y0im);  // conj ext.
            Ag[SWZ(f)]       = v1;
            Ag[SWZ(512 - f)] = v2;
        }
    }
    bar64(bid);

    // ---------------- inverse FFT + epilogue --------------------------------
    {   // inv stage 0: A -> C
        #pragma unroll
        for (int r = 0; r < 8; r++) a[r] = Ag[SWZ(t6 + 64 * r)];
        dft8p<1>(a);
        cpx b = s_tw[t6]; b.im ^= SGN2;    // conj base
        cpx w[8]; wpow7p(b, w);
        Cg[SWZ(8 * t6)] = a[0];
        #pragma unroll
        for (int u = 1; u < 8; u++) Cg[SWZ(8 * t6 + u)] = cmultw(a[u], w[u]);
    }
    bar64(bid);
    {   // inv stage 1: C -> A
        #pragma unroll
        for (int r = 0; r < 8; r++) a[r] = Cg[SWZ(q + 8 * p3 + 64 * r)];
        dft8p<1>(a);
        cpx b = s_tw[8 * p3]; b.im ^= SGN2;
        cpx w[8]; wpow7p(b, w);
        Ag[SWZ(q + 64 * p3)] = a[0];
        #pragma unroll
        for (int u = 1; u < 8; u++) Ag[SWZ(q + 64 * p3 + 8 * u)] = cmultw(a[u], w[u]);
    }
    bar64(bid);
    {   // inv stage 2 + bias + erf-GELU -> global
        #pragma unroll
        for (int r = 0; r < 8; r++) a[r] = Ag[SWZ(t6 + 64 * r)];
        dft8p<1>(a);
        const float* br = bias + j * 1024;
        float* o0 = out + tok0 * 4096 + j * 1024;
        float* o1 = o0 + 4096;
        #pragma unroll
        for (int u = 0; u < 8; u++) {
            int n = t6 + 64 * u;
            float r0, r1, i0, i1;
            up2(a[u].re, r0, r1);    // y_{2j}[n] for tok0, tok1
            up2(a[u].im, i0, i1);    // y_{2j+1}[n]
            float bn = br[n], bn2 = br[n + 512];
            o0[n]       = gelu_erf(r0 + bn);
            o1[n]       = gelu_erf(r1 + bn);
            o0[n + 512] = gelu_erf(i0 + bn2);
            o1[n + 512] = gelu_erf(i1 + bn2);
        }
    }
}

// ---------------- launch -----------------------------------------------------

extern "C" void kernel_launch(void* const* d_in, const int* in_sizes, int n_in,
                              void* d_out, int out_size) {
    const float* x         = (const float*)d_in[0];
    const float* w         = (const float*)d_in[1];
    const float* bias      = (const float*)d_in[2];
    const int*   sign_bits = (const int*)d_in[3];
    float* out = (float*)d_out;

    const int BS = in_sizes[0] / 4096;   // 8192 tokens

    const size_t smem = (size_t)(512 + 3 * 4 * 512) * sizeof(cpx) + 512;  // 107008 B
    cudaFuncSetAttribute(fused_main, cudaFuncAttributeMaxDynamicSharedMemorySize, (int)smem);

    precompute_tw_sf<<<1, 512>>>(sign_bits);
    precompute_wf<<<64, 256>>>(w);
    precompute_combine<<<(16 * NF + 255) / 256, 256>>>();
    fused_main<<<BS / 2, TPB, smem>>>(x, bias, out);
}

// round 17
// speedup vs baseline: 1.1356x; 1.1085x over previous
#include <cuda_runtime.h>
#include <cuda_bf16.h>
#include <math.h>

// FusedCirculantBlock R6: token-paired f32x2 FFT, 2-buffer ping-pong,
// launch_bounds(256,2) [the (256,3) variants killed the build container twice
// each — suspected ptxas spill explosion under the 84-reg cap].
// New vs R4b: C scratch buffer dropped (smem 107 -> 72.7 KB, bigger L1 carveout),
// mix weight loads software-pipelined one f-iteration ahead, bias preloaded
// before the inverse FFT so its L2 latency hides under 3 FFT stages.

typedef unsigned long long ull;

#define QB 8
#define NF 257
#define TPB 256
#define SGN2 0x8000000080000000ULL
#define NEG1_2 0xBF800000BF800000ULL   // (-1.0f, -1.0f)

__device__ float2   g_tw[512];        // (c, -s) scalar (precompute use)
__device__ float4   g_tw4[512];       // (c, c, -s, -s) packed
__device__ unsigned g_sfbits[128];
__device__ float2   g_Wf[64 * NF];    // scalar spectra [o*8+i][f], scaled 1/1024
__device__ float4   g_WA[16 * NF];    // (waE.re, waE.im, waO.re, waO.im) per (j*4+i, f)
__device__ float4   g_WB[16 * NF];

struct __align__(16) cpx { ull re, im; };

static __device__ __forceinline__ int SWZ(int i) { return i ^ ((i >> 3) & 7); }

static __device__ __forceinline__ void bar64(int id) {
    asm volatile("bar.sync %0, %1;" :: "r"(id), "r"(64) : "memory");
}

static __device__ __forceinline__ ull add2(ull a, ull b){ ull d; asm("add.rn.f32x2 %0,%1,%2;":"=l"(d):"l"(a),"l"(b)); return d; }
static __device__ __forceinline__ ull mul2(ull a, ull b){ ull d; asm("mul.rn.f32x2 %0,%1,%2;":"=l"(d):"l"(a),"l"(b)); return d; }
static __device__ __forceinline__ ull fma2(ull a, ull b, ull c){ ull d; asm("fma.rn.f32x2 %0,%1,%2,%3;":"=l"(d):"l"(a),"l"(b),"l"(c)); return d; }
// a - b == fma(b, -1, a): exact (mul by -1 exact, single rounding on the add)
static __device__ __forceinline__ ull sub2(ull a, ull b){ return fma2(b, NEG1_2, a); }
static __device__ __forceinline__ ull pk2(float x, float y){ ull d; asm("mov.b64 %0,{%1,%2};":"=l"(d):"f"(x),"f"(y)); return d; }
static __device__ __forceinline__ ull bc2(float x){ ull d; asm("mov.b64 %0,{%1,%1};":"=l"(d):"f"(x)); return d; }
static __device__ __forceinline__ void up2(ull a, float& x, float& y){ asm("mov.b64 {%0,%1},%2;":"=f"(x),"=f"(y):"l"(a)); }

static __device__ __forceinline__ float gelu_erf(float v) {
    return 0.5f * v * (1.0f + erff(v * 0.70710678118654752f));
}

// packed complex mul (general)
static __device__ __forceinline__ cpx cmulp(cpx a, cpx b) {
    cpx r;
    r.re = fma2(a.im ^ SGN2, b.im, mul2(a.re, b.re));
    r.im = fma2(a.im, b.re, mul2(a.re, b.im));
    return r;
}

// a * w, w = (wx + i*wy) packed per-component
static __device__ __forceinline__ cpx cmultw(cpx a, cpx w) {
    cpx r;
    r.re = fma2(a.im, w.im ^ SGN2, mul2(a.re, w.re));
    r.im = fma2(a.im, w.re, mul2(a.re, w.im));
    return r;
}

// 8-point DFT on token-packed data. INV=0 fwd (w8=e^{-2pi i/8}), INV=1 conj.
template <int INV>
static __device__ __forceinline__ void dft8p(cpx a[8]) {
    const ull C2  = 0x3F3504F33F3504F3ULL;   // ( c,  c), c = 1/sqrt(2)
    const ull C2N = 0xBF3504F3BF3504F3ULL;   // (-c, -c)
    cpx s0 = { add2(a[0].re, a[4].re), add2(a[0].im, a[4].im) };
    cpx s1 = { sub2(a[0].re, a[4].re), sub2(a[0].im, a[4].im) };
    cpx s2 = { add2(a[2].re, a[6].re), add2(a[2].im, a[6].im) };
    cpx s3 = { sub2(a[2].re, a[6].re), sub2(a[2].im, a[6].im) };
    cpx u0 = { add2(a[1].re, a[5].re), add2(a[1].im, a[5].im) };
    cpx u1 = { sub2(a[1].re, a[5].re), sub2(a[1].im, a[5].im) };
    cpx u2 = { add2(a[3].re, a[7].re), add2(a[3].im, a[7].im) };
    cpx u3 = { sub2(a[3].re, a[7].re), sub2(a[3].im, a[7].im) };
    cpx E0 = { add2(s0.re, s2.re), add2(s0.im, s2.im) };
    cpx E2 = { sub2(s0.re, s2.re), sub2(s0.im, s2.im) };
    cpx O0 = { add2(u0.re, u2.re), add2(u0.im, u2.im) };
    cpx O2 = { sub2(u0.re, u2.re), sub2(u0.im, u2.im) };
    cpx E1, E3, O1, O3, t1, t2, t3;
    if (!INV) {
        E1.re = add2(s1.re, s3.im); E1.im = sub2(s1.im, s3.re);   // s1 - i*s3
        E3.re = sub2(s1.re, s3.im); E3.im = add2(s1.im, s3.re);   // s1 + i*s3
        O1.re = add2(u1.re, u3.im); O1.im = sub2(u1.im, u3.re);
        O3.re = sub2(u1.re, u3.im); O3.im = add2(u1.im, u3.re);
        t1.re = mul2(add2(O1.re, O1.im), C2);  t1.im = mul2(sub2(O1.im, O1.re), C2);
        t2.re = O2.im;                         t2.im = O2.re ^ SGN2;
        t3.re = mul2(sub2(O3.im, O3.re), C2);  t3.im = mul2(add2(O3.re, O3.im), C2N);
    } else {
        E1.re = sub2(s1.re, s3.im); E1.im = add2(s1.im, s3.re);   // s1 + i*s3
        E3.re = add2(s1.re, s3.im); E3.im = sub2(s1.im, s3.re);
        O1.re = sub2(u1.re, u3.im); O1.im = add2(u1.im, u3.re);
        O3.re = add2(u1.re, u3.im); O3.im = sub2(u1.im, u3.re);
        t1.re = mul2(sub2(O1.re, O1.im), C2);  t1.im = mul2(add2(O1.re, O1.im), C2);
        t2.re = O2.im ^ SGN2;                  t2.im = O2.re;
        t3.re = mul2(add2(O3.re, O3.im), C2N); t3.im = mul2(sub2(O3.re, O3.im), C2);
    }
    a[0].re = add2(E0.re, O0.re); a[0].im = add2(E0.im, O0.im);
    a[4].re = sub2(E0.re, O0.re); a[4].im = sub2(E0.im, O0.im);
    a[1].re = add2(E1.re, t1.re); a[1].im = add2(E1.im, t1.im);
    a[5].re = sub2(E1.re, t1.re); a[5].im = sub2(E1.im, t1.im);
    a[2].re = add2(E2.re, t2.re); a[2].im = add2(E2.im, t2.im);
    a[6].re = sub2(E2.re, t2.re); a[6].im = sub2(E2.im, t2.im);
    a[3].re = add2(E3.re, t3.re); a[3].im = add2(E3.im, t3.im);
    a[7].re = sub2(E3.re, t3.re); a[7].im = sub2(E3.im, t3.im);
}

// Sequential-chain twiddled stores (straight-line, low register pressure).
// Stage-0 pattern: addr(u) = SWZ(8*t + u)
static __device__ __forceinline__ void store_tw_s0(cpx* buf, cpx a[8], cpx w1, int t) {
    buf[SWZ(8 * t)] = a[0];
    cpx w = w1;
    buf[SWZ(8 * t + 1)] = cmultw(a[1], w); w = cmulp(w, w1);
    buf[SWZ(8 * t + 2)] = cmultw(a[2], w); w = cmulp(w, w1);
    buf[SWZ(8 * t + 3)] = cmultw(a[3], w); w = cmulp(w, w1);
    buf[SWZ(8 * t + 4)] = cmultw(a[4], w); w = cmulp(w, w1);
    buf[SWZ(8 * t + 5)] = cmultw(a[5], w); w = cmulp(w, w1);
    buf[SWZ(8 * t + 6)] = cmultw(a[6], w); w = cmulp(w, w1);
    buf[SWZ(8 * t + 7)] = cmultw(a[7], w);
}
// Stage-1 pattern: addr(u) = SWZ(base + 8*u)
static __device__ __forceinline__ void store_tw_s1(cpx* buf, cpx a[8], cpx w1, int base) {
    buf[SWZ(base)] = a[0];
    cpx w = w1;
    buf[SWZ(base + 8)]  = cmultw(a[1], w); w = cmulp(w, w1);
    buf[SWZ(base + 16)] = cmultw(a[2], w); w = cmulp(w, w1);
    buf[SWZ(base + 24)] = cmultw(a[3], w); w = cmulp(w, w1);
    buf[SWZ(base + 32)] = cmultw(a[4], w); w = cmulp(w, w1);
    buf[SWZ(base + 40)] = cmultw(a[5], w); w = cmulp(w, w1);
    buf[SWZ(base + 48)] = cmultw(a[6], w); w = cmulp(w, w1);
    buf[SWZ(base + 56)] = cmultw(a[7], w);
}

// Mix helpers (plain functions; arrays become registers after inlining).
static __device__ __forceinline__ void loadW(float4 wa[4], float4 wb[4], int base, int f) {
    #pragma unroll
    for (int i = 0; i < 4; i++) {
        wa[i] = __ldg(&g_WA[(base + i) * NF + f]);
        wb[i] = __ldg(&g_WB[(base + i) * NF + f]);
    }
}

static __device__ __forceinline__ void mix_compute(const cpx* s_B, cpx* Ag, int f,
                                                   const float4 wa[4], const float4 wb[4]) {
    ull ReP0 = 0, ReM0 = 0, ImP0 = 0, ImM0 = 0;
    ull ReP1 = 0, ReM1 = 0, ImP1 = 0, ImM1 = 0;
    int fm = (512 - f) & 511;
    #pragma unroll
    for (int i = 0; i < 4; i++) {
        cpx zf = s_B[i * 512 + SWZ(f)];
        cpx zm = s_B[i * 512 + SWZ(fm)];
        ull ar0 = bc2(wa[i].x), ai0 = bc2(wa[i].y);
        ull br0 = bc2(wb[i].x), bi0 = bc2(wb[i].y);
        ull ar1 = bc2(wa[i].z), ai1 = bc2(wa[i].w);
        ull br1 = bc2(wb[i].z), bi1 = bc2(wb[i].w);
        // y += zf*wa  (re: +zr*ar -zi*ai ; im: +zr*ai +zi*ar)
        ReP0 = fma2(zf.re, ar0, ReP0); ReM0 = fma2(zf.im, ai0, ReM0);
        ImP0 = fma2(zf.re, ai0, ImP0); ImP0 = fma2(zf.im, ar0, ImP0);
        ReP1 = fma2(zf.re, ar1, ReP1); ReM1 = fma2(zf.im, ai1, ReM1);
        ImP1 = fma2(zf.re, ai1, ImP1); ImP1 = fma2(zf.im, ar1, ImP1);
        // y += conj(zm)*wb (re: +zr*br +zi*bi ; im: +zr*bi -zi*br)
        ReP0 = fma2(zm.re, br0, ReP0); ReP0 = fma2(zm.im, bi0, ReP0);
        ImP0 = fma2(zm.re, bi0, ImP0); ImM0 = fma2(zm.im, br0, ImM0);
        ReP1 = fma2(zm.re, br1, ReP1); ReP1 = fma2(zm.im, bi1, ReP1);
        ImP1 = fma2(zm.re, bi1, ImP1); ImM1 = fma2(zm.im, br1, ImM1);
    }
    ull y0re = sub2(ReP0, ReM0), y0im = sub2(ImP0, ImM0);
    ull y1re = sub2(ReP1, ReM1), y1im = sub2(ImP1, ImM1);
    if (f == 0 || f == 256) {
        cpx v; v.re = y0re; v.im = y1re;   // DC/Nyquist: imag analytically 0
        Ag[SWZ(f)] = v;
    } else {
        cpx v1; v1.re = sub2(y0re, y1im); v1.im = add2(y0im, y1re);  // Y0 + i*Y1
        cpx v2; v2.re = add2(y0re, y1im); v2.im = sub2(y1re, y0im);  // conj ext.
        Ag[SWZ(f)]       = v1;
        Ag[SWZ(512 - f)] = v2;
    }
}

// ---------------- precompute (in-graph, cheap) ------------------------------

__global__ void precompute_tw_sf(const int* __restrict__ sign_bits) {
    int k = threadIdx.x;  // 512
    float s, c;
    sincospif((float)k / 256.0f, &s, &c);
    g_tw[k]  = make_float2(c, -s);
    g_tw4[k] = make_float4(c, c, -s, -s);
    if (k < 128) {
        unsigned m = 0;
        #pragma unroll 4
        for (int b = 0; b < 32; b++)
            m |= ((unsigned)sign_bits[k * 32 + b] & 1u) << b;
        g_sfbits[k] = m;
    }
}

__global__ void precompute_wf(const float* __restrict__ w) {
    __shared__ float2 stw[512];
    __shared__ float  sw[512];
    int blk = blockIdx.x;  // o*8+i
    for (int k = threadIdx.x; k < 512; k += blockDim.x) {
        stw[k] = g_tw[k];
        sw[k] = w[blk * 512 + k];
    }
    __syncthreads();
    for (int f = threadIdx.x; f <= 256; f += blockDim.x) {
        float re = 0.0f, im = 0.0f;
        for (int n = 0; n < 512; n++) {
            float2 t = stw[(f * n) & 511];
            float wv = sw[n];
            re = fmaf(wv, t.x, re);
            im = fmaf(wv, t.y, im);
        }
        g_Wf[blk * NF + f] = make_float2(re * (1.0f / 1024.0f), im * (1.0f / 1024.0f));
    }
}

// Wa = W_{o,2i} - i*W_{o,2i+1},  Wb = W_{o,2i} + i*W_{o,2i+1};
// packed per (j,i,f) for outputs o = 2j (x,y) and o = 2j+1 (z,w).
__global__ void precompute_combine() {
    int idx = blockIdx.x * blockDim.x + threadIdx.x;
    if (idx >= 16 * NF) return;
    int f = idx % NF, r = idx / NF;
    int j = r >> 2, i = r & 3;
    float2 WE0 = g_Wf[((2 * j)     * QB + 2 * i)     * NF + f];
    float2 WO0 = g_Wf[((2 * j)     * QB + 2 * i + 1) * NF + f];
    float2 WE1 = g_Wf[((2 * j + 1) * QB + 2 * i)     * NF + f];
    float2 WO1 = g_Wf[((2 * j + 1) * QB + 2 * i + 1) * NF + f];
    g_WA[idx] = make_float4(WE0.x + WO0.y, WE0.y - WO0.x, WE1.x + WO1.y, WE1.y - WO1.x);
    g_WB[idx] = make_float4(WE0.x - WO0.y, WE0.y + WO0.x, WE1.x - WO1.y, WE1.y + WO1.x);
}

// ---------------- main fused kernel -----------------------------------------
// grid = BS/2, 256 thr, 2 CTAs/SM. Smem cpx slots (16B):
//   tw[512] | A[4*512] | B[4*512] | bits[128 u32]  = 74240 B

__global__ void __launch_bounds__(TPB, 2)
fused_main(const float* __restrict__ x, const float* __restrict__ bias,
           float* __restrict__ out) {
    extern __shared__ cpx sm[];
    cpx* s_tw = sm;                 // 512
    cpx* s_A  = sm + 512;           // 2048
    cpx* s_B  = sm + 512 + 2048;    // 2048
    unsigned* s_bits = (unsigned*)(sm + 512 + 4096);

    const int tid = threadIdx.x;
    const int j   = tid >> 6;        // group / output-pair id
    const int t6  = tid & 63;
    const int q   = t6 & 7, p3 = t6 >> 3;
    const int bid = j + 1;

    {
        float4* twd = (float4*)s_tw;
        for (int k = tid; k < 512; k += TPB) twd[k] = g_tw4[k];
        if (tid < 128) s_bits[tid] = g_sfbits[tid];
    }
    __syncthreads();

    const long long tok0 = (long long)blockIdx.x * 2;
    cpx* Ag = s_A + j * 512;
    cpx* Bg = s_B + j * 512;

    // ---------------- forward FFT (both tokens packed) ----------------
    cpx a[8];
    {   // stage 0: global load + sign flip + dft -> B
        const float* x0 = x + tok0 * 4096 + j * 1024;
        const float* x1 = x0 + 4096;
        #pragma unroll
        for (int r = 0; r < 8; r++) {
            int n = t6 + 64 * r;
            int e0 = j * 1024 + n, e1 = e0 + 512;
            ull m0 = (0ULL - (ull)((s_bits[e0 >> 5] >> (e0 & 31)) & 1u)) & SGN2;
            ull m1 = (0ULL - (ull)((s_bits[e1 >> 5] >> (e1 & 31)) & 1u)) & SGN2;
            a[r].re = pk2(x0[n],       x1[n])       ^ m0;
            a[r].im = pk2(x0[n + 512], x1[n + 512]) ^ m1;
        }
        dft8p<0>(a);
        store_tw_s0(Bg, a, s_tw[t6], t6);
    }
    bar64(bid);
    {   // stage 1: B -> A
        #pragma unroll
        for (int r = 0; r < 8; r++) a[r] = Bg[SWZ(q + 8 * p3 + 64 * r)];
        dft8p<0>(a);
        store_tw_s1(Ag, a, s_tw[8 * p3], q + 64 * p3);
    }
    bar64(bid);
    {   // stage 2: A -> B (no twiddles)
        #pragma unroll
        for (int r = 0; r < 8; r++) a[r] = Ag[SWZ(t6 + 64 * r)];
        dft8p<0>(a);
        #pragma unroll
        for (int u = 0; u < 8; u++) Bg[SWZ(t6 + 64 * u)] = a[u];
    }
    __syncthreads();   // all groups' Z in B (all-to-all read next); A dead

    // -------- mix (unpack folded in) + Hermitian pack -> A, software-pipelined
    {
        float4 wa[4], wb[4], na[4], nb[4];
        loadW(wa, wb, j * 4, t6);
        #pragma unroll
        for (int it = 0; it < 4; it++) {
            int f = t6 + it * 64;
            if (it < 3)           loadW(na, nb, j * 4, f + 64);
            else if (t6 == 0)     loadW(na, nb, j * 4, 256);
            mix_compute(s_B, Ag, f, wa, wb);
            #pragma unroll
            for (int k = 0; k < 4; k++) { wa[k] = na[k]; wb[k] = nb[k]; }
        }
        if (t6 == 0) mix_compute(s_B, Ag, 256, wa, wb);
    }
    __syncthreads();   // all groups done reading all of B; B reusable

    // ---- bias preload: issued now, consumed after 3 FFT stages (latency hidden)
    float bnv0[8], bnv1[8];
    {
        const float* br = bias + j * 1024;
        #pragma unroll
        for (int u = 0; u < 8; u++) {
            bnv0[u] = __ldg(&br[t6 + 64 * u]);
            bnv1[u] = __ldg(&br[t6 + 64 * u + 512]);
        }
    }

    // ---------------- inverse FFT + epilogue --------------------------------
    {   // inv stage 0: A -> B
        #pragma unroll
        for (int r = 0; r < 8; r++) a[r] = Ag[SWZ(t6 + 64 * r)];
        dft8p<1>(a);
        cpx b = s_tw[t6]; b.im ^= SGN2;    // conj base
        store_tw_s0(Bg, a, b, t6);
    }
    bar64(bid);
    {   // inv stage 1: B -> A
        #pragma unroll
        for (int r = 0; r < 8; r++) a[r] = Bg[SWZ(q + 8 * p3 + 64 * r)];
        dft8p<1>(a);
        cpx b = s_tw[8 * p3]; b.im ^= SGN2;
        store_tw_s1(Ag, a, b, q + 64 * p3);
    }
    bar64(bid);
    {   // inv stage 2 + bias + erf-GELU -> global
        #pragma unroll
        for (int r = 0; r < 8; r++) a[r] = Ag[SWZ(t6 + 64 * r)];
        dft8p<1>(a);
        float* o0 = out + tok0 * 4096 + j * 1024;
        float* o1 = o0 + 4096;
        #pragma unroll
        for (int u = 0; u < 8; u++) {
            int n = t6 + 64 * u;
            float r0, r1, i0, i1;
            up2(a[u].re, r0, r1);    // y_{2j}[n] for tok0, tok1
            up2(a[u].im, i0, i1);    // y_{2j+1}[n]
            o0[n]       = gelu_erf(r0 + bnv0[u]);
            o1[n]       = gelu_erf(r1 + bnv0[u]);
            o0[n + 512] = gelu_erf(i0 + bnv1[u]);
            o1[n + 512] = gelu_erf(i1 + bnv1[u]);
        }
    }
}

// ---------------- launch -----------------------------------------------------

extern "C" void kernel_launch(void* const* d_in, const int* in_sizes, int n_in,
                              void* d_out, int out_size) {
    const float* x         = (const float*)d_in[0];
    const float* w         = (const float*)d_in[1];
    const float* bias      = (const float*)d_in[2];
    const int*   sign_bits = (const int*)d_in[3];
    float* out = (float*)d_out;

    const int BS = in_sizes[0] / 4096;   // 8192 tokens

    const size_t smem = (size_t)(512 + 2 * 4 * 512) * sizeof(cpx) + 512;  // 74240 B
    cudaFuncSetAttribute(fused_main, cudaFuncAttributeMaxDynamicSharedMemorySize, (int)smem);

    precompute_tw_sf<<<1, 512>>>(sign_bits);
    precompute_wf<<<64, 256>>>(w);
    precompute_combine<<<(16 * NF + 255) / 256, 256>>>();
    fused_main<<<BS / 2, TPB, smem>>>(x, bias, out);
}